// round 13
// baseline (speedup 1.0000x reference)
#include <cuda_runtime.h>
#include <cuda_fp16.h>
#include <math_constants.h>
#include <cstdint>

#define N_FILT 80
#define FDIM   251
#define L_IN   64000
#define P_OUT  63750
#define N_BATCH 8

#define MPAD   128
#define KPAD   256
#define NT     384          // positions per CTA (8 warps x 48)
#define THREADS 256
#define NSTEPS  16          // KPAD / 16
#define NJ      6           // n8 tiles per warp

// A row stride padded to 528B (264 halves): 132 words = 4 banks shift/row
#define A_STRIDE_B 528
// dynamic smem layout (bytes); sized for the NI=3 (48-row) group
#define WS_OFF   0
#define XC_OFF   25344      // 48 * 528
#define XO_OFF   26688      // +1344 B = 336 words = +16 banks (mod 32)
#define SMEM_TOTAL 28032
#define XBUF 648            // halves: NT + 256 + slack

__device__ float  g_filters[N_FILT][FDIM];
__device__ __half g_wh[MPAD][KPAD];   // zero-initialized; rows >=80 stay zero

// ============================ PTX helpers ============================
__device__ __forceinline__ uint32_t smem_u32(const void* p) {
    uint32_t a;
    asm("{ .reg .u64 t; cvta.to.shared.u64 t, %1; cvt.u32.u64 %0, t; }"
        : "=r"(a) : "l"(p));
    return a;
}
__device__ __forceinline__ uint32_t lds32(uint32_t a) {
    uint32_t v;
    asm volatile("ld.shared.b32 %0, [%1];" : "=r"(v) : "r"(a));
    return v;
}
__device__ __forceinline__ void ldsm4(uint32_t* r, uint32_t a) {
    asm volatile("ldmatrix.sync.aligned.m8n8.x4.shared.b16 {%0,%1,%2,%3}, [%4];"
                 : "=r"(r[0]), "=r"(r[1]), "=r"(r[2]), "=r"(r[3]) : "r"(a));
}
__device__ __forceinline__ void mma16816(float* d, const uint32_t* a,
                                         uint32_t b0, uint32_t b1) {
    asm volatile(
        "mma.sync.aligned.m16n8k16.row.col.f32.f16.f16.f32 "
        "{%0,%1,%2,%3}, {%4,%5,%6,%7}, {%8,%9}, {%0,%1,%2,%3};"
        : "+f"(d[0]), "+f"(d[1]), "+f"(d[2]), "+f"(d[3])
        : "r"(a[0]), "r"(a[1]), "r"(a[2]), "r"(a[3]), "r"(b0), "r"(b1));
}

// ========================= filter construction =========================
#define BF_THREADS 256
__device__ __forceinline__ float blk_reduce(float v, int mode) {
    __shared__ float part[8];
    const int lane = threadIdx.x & 31, w = threadIdx.x >> 5;
    #pragma unroll
    for (int off = 16; off; off >>= 1) {
        float o = __shfl_xor_sync(0xffffffffu, v, off);
        v = (mode == 0) ? fmaxf(v, o) : (mode == 1) ? fminf(v, o) : (v + o);
    }
    __syncthreads();
    if (lane == 0) part[w] = v;
    __syncthreads();
    float r = part[0];
    #pragma unroll
    for (int k = 1; k < 8; k++) {
        float o = part[k];
        r = (mode == 0) ? fmaxf(r, o) : (mode == 1) ? fminf(r, o) : (r + o);
    }
    return r;
}
__device__ __forceinline__ float norm_pm1(float v, bool act) {
    float mx = blk_reduce(act ? v : -CUDART_INF_F, 0);
    float mn = blk_reduce(act ? v :  CUDART_INF_F, 1);
    float y  = 2.0f * (v - mn) / (mx - mn + 1e-6f) - 1.0f;
    float s  = blk_reduce(act ? y : 0.0f, 2);
    return y - s * (1.0f / (float)FDIM);
}

__global__ void build_filters_kernel(const float* __restrict__ nf1,
                                     const float* __restrict__ nf2,
                                     const float* __restrict__ nf3,
                                     const float* __restrict__ nf4,
                                     const float* __restrict__ amp1,
                                     const float* __restrict__ amp2) {
    __shared__ float ir1[FDIM];
    __shared__ float ir2[FDIM];
    const int f = blockIdx.x;
    const int i = threadIdx.x;
    const bool act = (i < FDIM);
    const float FS = 16000.0f, MF = 50.0f / 16000.0f;
    const float PIF = 3.14159265358979323846f, TWO_PI = 6.28318530717958647692f;

    float f1 = fminf(fmaxf(fabsf(nf1[f]) + MF, 0.0f), 0.5f);
    float f2 = fminf(fmaxf(f1 + fabsf(nf2[f] - f1) + MF, 0.0f), 0.5f);
    float f3 = fminf(fmaxf(fabsf(nf3[f]) + MF, 0.0f), 0.5f);
    float f4 = fminf(fmaxf(f3 + fabsf(nf4[f] - f3) + MF, 0.0f), 0.5f);
    float a1 = fabsf(amp1[f]), a2 = fabsf(amp2[f]);
    float ti = act ? (float)(i + 1) * (1.0f / FS) : 0.0f;
    float t2 = ti * ti;
    {
        float F1 = f1 * FS, F2 = f2 * FS, fc = 0.5f * (F1 + F2), bw = F2 - F1;
        float pb = PIF * bw, ce = -2.0f * pb * pb;
        float v = a1 * expf(ce * t2) * cosf((TWO_PI * fc) * ti);
        v = norm_pm1(v, act);
        if (act) ir1[i] = v;
    }
    {
        float F1 = f3 * FS, F2 = f4 * FS, fc = 0.5f * (F1 + F2), bw = F2 - F1;
        float pb = PIF * bw, ce = -2.0f * pb * pb;
        float v = a2 * expf(ce * t2) * cosf((TWO_PI * fc) * ti);
        v = norm_pm1(v, act);
        if (act) ir2[i] = v;
    }
    __syncthreads();
    float c = 0.0f;
    if (act) {
        #pragma unroll 4
        for (int j = 0; j < FDIM; j++) {
            int idx = i + j - (FDIM / 2);
            if (idx >= 0 && idx < FDIM) c += ir1[idx] * ir2[j];
        }
    }
    c = norm_pm1(c, act);
    if (act) {
        float nv  = (float)i * ((float)FDIM / (float)(FDIM - 1));
        float win = 0.54f - 0.46f * cosf(TWO_PI * nv * (1.0f / (float)FDIM));
        float w = c * win;
        g_filters[f][i] = w;
        g_wh[f][i] = __float2half_rn(w);
    } else if (i < KPAD) {
        g_wh[f][i] = __ushort_as_half(0);   // zero K tail 251..255
    }
}

// ========================= main HMMA conv =========================
extern __shared__ __align__(16) char smraw[];

template <int NI>
__device__ __forceinline__ void conv_body(char* smraw_p, const float* __restrict__ x,
                                          float* __restrict__ out, int f0base) {
    const int t   = threadIdx.x;
    const int wid = t >> 5;
    const int lid = t & 31;
    const int gid = lid >> 2;      // 0..7
    const int tg  = lid & 3;       // 0..3
    const int n0  = blockIdx.x * NT;
    const int b   = blockIdx.y;
    const int nw  = wid * (NJ * 8);   // warp's position offset (48)

    const uint32_t sbase = smem_u32(smraw_p);

    // ---- stage this group's weight rows (NI*16), 528B padded stride ----
    {
        const uint2* gh = reinterpret_cast<const uint2*>(&g_wh[f0base][0]);
        const int chunks = NI * 16 * 64;         // uint2 per group
        for (int idx = t; idx < chunks; idx += THREADS) {
            int m = idx >> 6, c = idx & 63;
            uint2 vh = gh[m * 64 + c];
            *reinterpret_cast<uint2*>(smraw_p + WS_OFF + m * A_STRIDE_B + c * 8) = vh;
        }
    }
    // ---- load x window (fp16), plus 1-half-shifted copy ----
    {
        const float* xb = x + (size_t)b * L_IN;
        __half* xc = reinterpret_cast<__half*>(smraw_p + XC_OFF);
        __half* xo = reinterpret_cast<__half*>(smraw_p + XO_OFF);
        for (int i = t; i < XBUF; i += THREADS) {
            int g  = n0 + i;
            float v  = (g < L_IN) ? xb[g] : 0.0f;
            int g2 = g + 1;
            float v2 = (g2 < L_IN) ? xb[g2] : 0.0f;
            xc[i] = __float2half_rn(v);
            xo[i] = __float2half_rn(v2);
        }
    }
    __syncthreads();

    // ---- per-lane address bases ----
    const int sub = lid >> 3;
    const uint32_t a_base = sbase + WS_OFF
        + (uint32_t)(((lid & 7) + (sub & 1) * 8) * A_STRIDE_B + (sub >> 1) * 16);
    const int sel = gid & 1;
    const uint32_t b_base = sbase + (sel ? XO_OFF : XC_OFF)
        + (uint32_t)(2 * (2 * tg + nw + gid - sel));

    float acc[NI][NJ][4];
    #pragma unroll
    for (int i = 0; i < NI; i++)
        #pragma unroll
        for (int j = 0; j < NJ; j++)
            #pragma unroll
            for (int c = 0; c < 4; c++) acc[i][j][c] = 0.0f;

    #pragma unroll 2
    for (int s = 0; s < NSTEPS; s++) {
        const uint32_t kb = (uint32_t)s * 32;   // k0 * 2 bytes

        uint32_t bh[NJ + 1];
        #pragma unroll
        for (int j = 0; j < NJ + 1; j++) {
            bh[j] = lds32(b_base + kb + (uint32_t)(j * 16));
        }

        #pragma unroll
        for (int i = 0; i < NI; i++) {
            uint32_t ah[4];
            ldsm4(ah, a_base + (uint32_t)(i * 16 * A_STRIDE_B) + kb);
            #pragma unroll
            for (int j = 0; j < NJ; j++) {
                mma16816(acc[i][j], ah, bh[j], bh[j + 1]);
            }
        }
    }

    // ---- epilogue: direct stores from fragments ----
    #pragma unroll
    for (int i = 0; i < NI; i++) {
        const int f0 = f0base + 16 * i + gid;
        float* o0 = out + ((size_t)b * N_FILT + f0) * P_OUT;
        float* o1 = out + ((size_t)b * N_FILT + f0 + 8) * P_OUT;
        #pragma unroll
        for (int j = 0; j < NJ; j++) {
            int p = n0 + nw + 8 * j + 2 * tg;
            if (p < P_OUT) {
                *reinterpret_cast<float2*>(o0 + p) =
                    make_float2(acc[i][j][0], acc[i][j][1]);
                *reinterpret_cast<float2*>(o1 + p) =
                    make_float2(acc[i][j][2], acc[i][j][3]);
            }
        }
    }
}

__global__ __launch_bounds__(THREADS, 3) void conv_mma_kernel(const float* __restrict__ x,
                                                              float* __restrict__ out) {
    if (blockIdx.z == 0) {
        conv_body<3>(smraw, x, out, 0);    // filters 0..47
    } else {
        conv_body<2>(smraw, x, out, 48);   // filters 48..79
    }
}

// ================================ launch ================================
extern "C" void kernel_launch(void* const* d_in, const int* in_sizes, int n_in,
                              void* d_out, int out_size) {
    const float* x    = (const float*)d_in[0];
    const float* nf1  = (const float*)d_in[1];
    const float* nf2  = (const float*)d_in[2];
    const float* nf3  = (const float*)d_in[3];
    const float* nf4  = (const float*)d_in[4];
    const float* amp1 = (const float*)d_in[5];
    const float* amp2 = (const float*)d_in[6];
    float* out = (float*)d_out;

    static bool attr_set = false;
    if (!attr_set) {
        cudaFuncSetAttribute(conv_mma_kernel,
                             cudaFuncAttributeMaxDynamicSharedMemorySize, SMEM_TOTAL);
        attr_set = true;
    }

    build_filters_kernel<<<N_FILT, BF_THREADS>>>(nf1, nf2, nf3, nf4, amp1, amp2);

    dim3 grid((P_OUT + NT - 1) / NT, N_BATCH, 2);   // 167 x 8 x 2
    conv_mma_kernel<<<grid, THREADS, SMEM_TOTAL>>>(x, out);
}

// round 14
// speedup vs baseline: 1.4156x; 1.4156x over previous
#include <cuda_runtime.h>
#include <cuda_fp16.h>
#include <math_constants.h>
#include <cstdint>

#define N_FILT 80
#define FDIM   251
#define L_IN   64000
#define P_OUT  63750
#define N_BATCH 8

#define MPAD   128
#define KPAD   256
#define NT     256          // positions per work item (8 warps x 32)
#define THREADS 256
#define NSTEPS  16          // KPAD / 16
#define NJ      4           // n8 tiles per warp
#define NI      5           // m16 tiles per warp

#define N_TILES 250         // ceil(P_OUT / NT)
#define N_ITEMS (N_TILES * N_BATCH)   // 2000
#define GRID_X  296         // 2 CTAs per SM x 148 SMs

// A row stride padded to 528B (264 halves): 132 words = 4 banks shift/row
#define A_STRIDE_B 528
// dynamic smem layout (bytes)
#define WS_OFF   0
#define XC_OFF   42240      // 80 * 528
#define XO_OFF   43328      // +1088 B = 272 words = +16 banks (mod 32)
#define SMEM_TOTAL 44416
#define XBUF 528

__device__ float  g_filters[N_FILT][FDIM];
__device__ __half g_wh[MPAD][KPAD];   // zero-initialized; rows >=80 stay zero

// ============================ PTX helpers ============================
__device__ __forceinline__ uint32_t smem_u32(const void* p) {
    uint32_t a;
    asm("{ .reg .u64 t; cvta.to.shared.u64 t, %1; cvt.u32.u64 %0, t; }"
        : "=r"(a) : "l"(p));
    return a;
}
__device__ __forceinline__ uint32_t lds32(uint32_t a) {
    uint32_t v;
    asm volatile("ld.shared.b32 %0, [%1];" : "=r"(v) : "r"(a));
    return v;
}
__device__ __forceinline__ void ldsm4(uint32_t* r, uint32_t a) {
    asm volatile("ldmatrix.sync.aligned.m8n8.x4.shared.b16 {%0,%1,%2,%3}, [%4];"
                 : "=r"(r[0]), "=r"(r[1]), "=r"(r[2]), "=r"(r[3]) : "r"(a));
}
__device__ __forceinline__ void mma16816(float* d, const uint32_t* a,
                                         uint32_t b0, uint32_t b1) {
    asm volatile(
        "mma.sync.aligned.m16n8k16.row.col.f32.f16.f16.f32 "
        "{%0,%1,%2,%3}, {%4,%5,%6,%7}, {%8,%9}, {%0,%1,%2,%3};"
        : "+f"(d[0]), "+f"(d[1]), "+f"(d[2]), "+f"(d[3])
        : "r"(a[0]), "r"(a[1]), "r"(a[2]), "r"(a[3]), "r"(b0), "r"(b1));
}

// ========================= filter construction =========================
#define BF_THREADS 256
__device__ __forceinline__ float blk_reduce(float v, int mode) {
    __shared__ float part[8];
    const int lane = threadIdx.x & 31, w = threadIdx.x >> 5;
    #pragma unroll
    for (int off = 16; off; off >>= 1) {
        float o = __shfl_xor_sync(0xffffffffu, v, off);
        v = (mode == 0) ? fmaxf(v, o) : (mode == 1) ? fminf(v, o) : (v + o);
    }
    __syncthreads();
    if (lane == 0) part[w] = v;
    __syncthreads();
    float r = part[0];
    #pragma unroll
    for (int k = 1; k < 8; k++) {
        float o = part[k];
        r = (mode == 0) ? fmaxf(r, o) : (mode == 1) ? fminf(r, o) : (r + o);
    }
    return r;
}
__device__ __forceinline__ float norm_pm1(float v, bool act) {
    float mx = blk_reduce(act ? v : -CUDART_INF_F, 0);
    float mn = blk_reduce(act ? v :  CUDART_INF_F, 1);
    float y  = 2.0f * (v - mn) / (mx - mn + 1e-6f) - 1.0f;
    float s  = blk_reduce(act ? y : 0.0f, 2);
    return y - s * (1.0f / (float)FDIM);
}

__global__ void build_filters_kernel(const float* __restrict__ nf1,
                                     const float* __restrict__ nf2,
                                     const float* __restrict__ nf3,
                                     const float* __restrict__ nf4,
                                     const float* __restrict__ amp1,
                                     const float* __restrict__ amp2) {
    __shared__ float ir1[FDIM];
    __shared__ float ir2[FDIM];
    const int f = blockIdx.x;
    const int i = threadIdx.x;
    const bool act = (i < FDIM);
    const float FS = 16000.0f, MF = 50.0f / 16000.0f;
    const float PIF = 3.14159265358979323846f, TWO_PI = 6.28318530717958647692f;

    float f1 = fminf(fmaxf(fabsf(nf1[f]) + MF, 0.0f), 0.5f);
    float f2 = fminf(fmaxf(f1 + fabsf(nf2[f] - f1) + MF, 0.0f), 0.5f);
    float f3 = fminf(fmaxf(fabsf(nf3[f]) + MF, 0.0f), 0.5f);
    float f4 = fminf(fmaxf(f3 + fabsf(nf4[f] - f3) + MF, 0.0f), 0.5f);
    float a1 = fabsf(amp1[f]), a2 = fabsf(amp2[f]);
    float ti = act ? (float)(i + 1) * (1.0f / FS) : 0.0f;
    float t2 = ti * ti;
    {
        float F1 = f1 * FS, F2 = f2 * FS, fc = 0.5f * (F1 + F2), bw = F2 - F1;
        float pb = PIF * bw, ce = -2.0f * pb * pb;
        float v = a1 * expf(ce * t2) * cosf((TWO_PI * fc) * ti);
        v = norm_pm1(v, act);
        if (act) ir1[i] = v;
    }
    {
        float F1 = f3 * FS, F2 = f4 * FS, fc = 0.5f * (F1 + F2), bw = F2 - F1;
        float pb = PIF * bw, ce = -2.0f * pb * pb;
        float v = a2 * expf(ce * t2) * cosf((TWO_PI * fc) * ti);
        v = norm_pm1(v, act);
        if (act) ir2[i] = v;
    }
    __syncthreads();
    float c = 0.0f;
    if (act) {
        #pragma unroll 4
        for (int j = 0; j < FDIM; j++) {
            int idx = i + j - (FDIM / 2);
            if (idx >= 0 && idx < FDIM) c += ir1[idx] * ir2[j];
        }
    }
    c = norm_pm1(c, act);
    if (act) {
        float nv  = (float)i * ((float)FDIM / (float)(FDIM - 1));
        float win = 0.54f - 0.46f * cosf(TWO_PI * nv * (1.0f / (float)FDIM));
        float w = c * win;
        g_filters[f][i] = w;
        g_wh[f][i] = __float2half_rn(w);
    } else if (i < KPAD) {
        g_wh[f][i] = __ushort_as_half(0);   // zero K tail 251..255
    }
}

// ========================= main HMMA conv (persistent CTAs) =========================
extern __shared__ __align__(16) char smraw[];

__global__ __launch_bounds__(THREADS, 2) void conv_mma_kernel(const float* __restrict__ x,
                                                              float* __restrict__ out) {
    const int t   = threadIdx.x;
    const int wid = t >> 5;
    const int lid = t & 31;
    const int gid = lid >> 2;      // 0..7
    const int tg  = lid & 3;       // 0..3
    const int nw  = wid * 32;      // warp's position offset within tile

    const uint32_t sbase = smem_u32(smraw);

    // ---- stage fp16 weights ONCE (528B padded row stride) ----
    {
        const uint2* gh = reinterpret_cast<const uint2*>(&g_wh[0][0]);
        #pragma unroll
        for (int i = 0; i < 20; i++) {
            int idx = t + i * THREADS;          // 0..5119
            int m = idx >> 6, c = idx & 63;
            uint2 vh = gh[m * 64 + c];
            *reinterpret_cast<uint2*>(smraw + WS_OFF + m * A_STRIDE_B + c * 8) = vh;
        }
    }

    // ---- per-lane address bases (constant across items) ----
    const int sub = lid >> 3;
    const uint32_t a_base = sbase + WS_OFF
        + (uint32_t)(((lid & 7) + (sub & 1) * 8) * A_STRIDE_B + (sub >> 1) * 16);
    const int sel = gid & 1;
    const uint32_t b_base = sbase + (sel ? XO_OFF : XC_OFF)
        + (uint32_t)(2 * (2 * tg + nw + gid - sel));

    __half* const xc = reinterpret_cast<__half*>(smraw + XC_OFF);
    __half* const xo = reinterpret_cast<__half*>(smraw + XO_OFF);

    // ---- persistent loop over (tile, batch) work items ----
    for (int item = blockIdx.x; item < N_ITEMS; item += GRID_X) {
        const int b    = item / N_TILES;
        const int tile = item - b * N_TILES;
        const int n0   = tile * NT;

        __syncthreads();   // WAR: previous item's readers done before overwrite
        {
            const float* xb = x + (size_t)b * L_IN;
            for (int i = t; i < XBUF; i += THREADS) {
                int g  = n0 + i;
                float v  = (g < L_IN) ? xb[g] : 0.0f;
                int g2 = g + 1;
                float v2 = (g2 < L_IN) ? xb[g2] : 0.0f;
                xc[i] = __float2half_rn(v);
                xo[i] = __float2half_rn(v2);
            }
        }
        __syncthreads();   // x window (and, first item, weights) visible

        float acc[NI][NJ][4];
        #pragma unroll
        for (int i = 0; i < NI; i++)
            #pragma unroll
            for (int j = 0; j < NJ; j++)
                #pragma unroll
                for (int c = 0; c < 4; c++) acc[i][j][c] = 0.0f;

        #pragma unroll 2
        for (int s = 0; s < NSTEPS; s++) {
            const uint32_t kb = (uint32_t)s * 32;   // k0 * 2 bytes

            uint32_t bh[NJ + 1];
            #pragma unroll
            for (int j = 0; j < NJ + 1; j++) {
                bh[j] = lds32(b_base + kb + (uint32_t)(j * 16));
            }

            #pragma unroll
            for (int i = 0; i < NI; i++) {
                uint32_t ah[4];
                ldsm4(ah, a_base + (uint32_t)(i * 16 * A_STRIDE_B) + kb);
                #pragma unroll
                for (int j = 0; j < NJ; j++) {
                    mma16816(acc[i][j], ah, bh[j], bh[j + 1]);
                }
            }
        }

        // ---- epilogue: direct stores from fragments ----
        #pragma unroll
        for (int i = 0; i < NI; i++) {
            const int f0 = 16 * i + gid;
            float* o0 = out + ((size_t)b * N_FILT + f0) * P_OUT;
            float* o1 = out + ((size_t)b * N_FILT + f0 + 8) * P_OUT;
            #pragma unroll
            for (int j = 0; j < NJ; j++) {
                int p = n0 + nw + 8 * j + 2 * tg;
                if (p < P_OUT) {
                    *reinterpret_cast<float2*>(o0 + p) =
                        make_float2(acc[i][j][0], acc[i][j][1]);
                    *reinterpret_cast<float2*>(o1 + p) =
                        make_float2(acc[i][j][2], acc[i][j][3]);
                }
            }
        }
    }
}

// ================================ launch ================================
extern "C" void kernel_launch(void* const* d_in, const int* in_sizes, int n_in,
                              void* d_out, int out_size) {
    const float* x    = (const float*)d_in[0];
    const float* nf1  = (const float*)d_in[1];
    const float* nf2  = (const float*)d_in[2];
    const float* nf3  = (const float*)d_in[3];
    const float* nf4  = (const float*)d_in[4];
    const float* amp1 = (const float*)d_in[5];
    const float* amp2 = (const float*)d_in[6];
    float* out = (float*)d_out;

    static bool attr_set = false;
    if (!attr_set) {
        cudaFuncSetAttribute(conv_mma_kernel,
                             cudaFuncAttributeMaxDynamicSharedMemorySize, SMEM_TOTAL);
        attr_set = true;
    }

    build_filters_kernel<<<N_FILT, BF_THREADS>>>(nf1, nf2, nf3, nf4, amp1, amp2);

    conv_mma_kernel<<<GRID_X, THREADS, SMEM_TOTAL>>>(x, out);
}

// round 15
// speedup vs baseline: 1.8108x; 1.2791x over previous
#include <cuda_runtime.h>
#include <cuda_fp16.h>
#include <math_constants.h>
#include <cstdint>

#define N_FILT 80
#define FDIM   251
#define L_IN   64000
#define P_OUT  63750
#define N_BATCH 8

#define MPAD   128
#define KPAD   256
#define NT     256          // positions per CTA (8 warps x 32)
#define THREADS 256
#define NSTEPS  16          // KPAD / 16
#define NJ      4           // n8 tiles per warp
#define NI      5           // m16 tiles per warp

// A row stride padded to 528B (264 halves): 132 words = 4 banks shift/row
#define A_STRIDE_B 528
// dynamic smem layout (bytes)
#define WS_OFF   0
#define XC_OFF   42240      // 80 * 528
#define XO_OFF   43328      // +1088 B = 272 words = +16 banks (mod 32)
#define EPI_OFF  44416      // per-warp transpose buffers: 8 x 2560 B
#define EPI_WARP_B 2560     // 16 rows x 40 words x 4 B
#define SMEM_TOTAL (EPI_OFF + 8 * EPI_WARP_B)   // 64896
#define XBUF 528

__device__ __half g_wh[MPAD][KPAD];   // zero-initialized; rows >=80 stay zero

// ============================ PTX helpers ============================
__device__ __forceinline__ uint32_t smem_u32(const void* p) {
    uint32_t a;
    asm("{ .reg .u64 t; cvta.to.shared.u64 t, %1; cvt.u32.u64 %0, t; }"
        : "=r"(a) : "l"(p));
    return a;
}
__device__ __forceinline__ uint32_t lds32(uint32_t a) {
    uint32_t v;
    asm volatile("ld.shared.b32 %0, [%1];" : "=r"(v) : "r"(a));
    return v;
}
__device__ __forceinline__ void sts_v2(uint32_t a, float x, float y) {
    asm volatile("st.shared.v2.f32 [%0], {%1, %2};" :: "r"(a), "f"(x), "f"(y) : "memory");
}
__device__ __forceinline__ float2 lds_v2(uint32_t a) {
    float2 v;
    asm volatile("ld.shared.v2.f32 {%0, %1}, [%2];" : "=f"(v.x), "=f"(v.y) : "r"(a));
    return v;
}
__device__ __forceinline__ void ldsm4(uint32_t* r, uint32_t a) {
    asm volatile("ldmatrix.sync.aligned.m8n8.x4.shared.b16 {%0,%1,%2,%3}, [%4];"
                 : "=r"(r[0]), "=r"(r[1]), "=r"(r[2]), "=r"(r[3]) : "r"(a));
}
__device__ __forceinline__ void mma16816(float* d, const uint32_t* a,
                                         uint32_t b0, uint32_t b1) {
    asm volatile(
        "mma.sync.aligned.m16n8k16.row.col.f32.f16.f16.f32 "
        "{%0,%1,%2,%3}, {%4,%5,%6,%7}, {%8,%9}, {%0,%1,%2,%3};"
        : "+f"(d[0]), "+f"(d[1]), "+f"(d[2]), "+f"(d[3])
        : "r"(a[0]), "r"(a[1]), "r"(a[2]), "r"(a[3]), "r"(b0), "r"(b1));
}

// ========================= filter construction =========================
#define BF_THREADS 256
__device__ __forceinline__ float blk_reduce(float v, int mode) {
    __shared__ float part[8];
    const int lane = threadIdx.x & 31, w = threadIdx.x >> 5;
    #pragma unroll
    for (int off = 16; off; off >>= 1) {
        float o = __shfl_xor_sync(0xffffffffu, v, off);
        v = (mode == 0) ? fmaxf(v, o) : (mode == 1) ? fminf(v, o) : (v + o);
    }
    __syncthreads();
    if (lane == 0) part[w] = v;
    __syncthreads();
    float r = part[0];
    #pragma unroll
    for (int k = 1; k < 8; k++) {
        float o = part[k];
        r = (mode == 0) ? fmaxf(r, o) : (mode == 1) ? fminf(r, o) : (r + o);
    }
    return r;
}
__device__ __forceinline__ float norm_pm1(float v, bool act) {
    float mx = blk_reduce(act ? v : -CUDART_INF_F, 0);
    float mn = blk_reduce(act ? v :  CUDART_INF_F, 1);
    float y  = 2.0f * (v - mn) / (mx - mn + 1e-6f) - 1.0f;
    float s  = blk_reduce(act ? y : 0.0f, 2);
    return y - s * (1.0f / (float)FDIM);
}

__global__ void build_filters_kernel(const float* __restrict__ nf1,
                                     const float* __restrict__ nf2,
                                     const float* __restrict__ nf3,
                                     const float* __restrict__ nf4,
                                     const float* __restrict__ amp1,
                                     const float* __restrict__ amp2) {
    __shared__ float ir1[FDIM];
    __shared__ float ir2[FDIM];
    const int f = blockIdx.x;
    const int i = threadIdx.x;
    const bool act = (i < FDIM);
    const float FS = 16000.0f, MF = 50.0f / 16000.0f;
    const float PIF = 3.14159265358979323846f, TWO_PI = 6.28318530717958647692f;

    float f1 = fminf(fmaxf(fabsf(nf1[f]) + MF, 0.0f), 0.5f);
    float f2 = fminf(fmaxf(f1 + fabsf(nf2[f] - f1) + MF, 0.0f), 0.5f);
    float f3 = fminf(fmaxf(fabsf(nf3[f]) + MF, 0.0f), 0.5f);
    float f4 = fminf(fmaxf(f3 + fabsf(nf4[f] - f3) + MF, 0.0f), 0.5f);
    float a1 = fabsf(amp1[f]), a2 = fabsf(amp2[f]);
    float ti = act ? (float)(i + 1) * (1.0f / FS) : 0.0f;
    float t2 = ti * ti;
    {
        float F1 = f1 * FS, F2 = f2 * FS, fc = 0.5f * (F1 + F2), bw = F2 - F1;
        float pb = PIF * bw, ce = -2.0f * pb * pb;
        float v = a1 * expf(ce * t2) * cosf((TWO_PI * fc) * ti);
        v = norm_pm1(v, act);
        if (act) ir1[i] = v;
    }
    {
        float F1 = f3 * FS, F2 = f4 * FS, fc = 0.5f * (F1 + F2), bw = F2 - F1;
        float pb = PIF * bw, ce = -2.0f * pb * pb;
        float v = a2 * expf(ce * t2) * cosf((TWO_PI * fc) * ti);
        v = norm_pm1(v, act);
        if (act) ir2[i] = v;
    }
    __syncthreads();
    float c = 0.0f;
    if (act) {
        #pragma unroll 4
        for (int j = 0; j < FDIM; j++) {
            int idx = i + j - (FDIM / 2);
            if (idx >= 0 && idx < FDIM) c += ir1[idx] * ir2[j];
        }
    }
    c = norm_pm1(c, act);
    if (act) {
        float nv  = (float)i * ((float)FDIM / (float)(FDIM - 1));
        float win = 0.54f - 0.46f * cosf(TWO_PI * nv * (1.0f / (float)FDIM));
        g_wh[f][i] = __float2half_rn(c * win);
    } else if (i < KPAD) {
        g_wh[f][i] = __ushort_as_half(0);   // zero K tail 251..255
    }
}

// ========================= main HMMA conv =========================
extern __shared__ __align__(16) char smraw[];

__global__ __launch_bounds__(THREADS, 2) void conv_mma_kernel(const float* __restrict__ x,
                                                              float* __restrict__ out) {
    const int t   = threadIdx.x;
    const int wid = t >> 5;
    const int lid = t & 31;
    const int gid = lid >> 2;      // 0..7
    const int tg  = lid & 3;       // 0..3
    const int n0  = blockIdx.x * NT;
    const int b   = blockIdx.y;
    const int nw  = wid * 32;      // warp's position offset within tile

    const uint32_t sbase = smem_u32(smraw);

    // ---- load fp16 weights into smem, 528B padded row stride ----
    {
        const uint2* gh = reinterpret_cast<const uint2*>(&g_wh[0][0]);
        #pragma unroll
        for (int i = 0; i < 20; i++) {
            int idx = t + i * THREADS;          // 0..5119
            int m = idx >> 6, c = idx & 63;
            uint2 vh = gh[m * 64 + c];
            *reinterpret_cast<uint2*>(smraw + WS_OFF + m * A_STRIDE_B + c * 8) = vh;
        }
    }
    // ---- load x window (fp16), plus 1-half-shifted copy ----
    {
        const float* xb = x + (size_t)b * L_IN;
        __half* xc = reinterpret_cast<__half*>(smraw + XC_OFF);
        __half* xo = reinterpret_cast<__half*>(smraw + XO_OFF);
        #pragma unroll
        for (int i = t; i < XBUF; i += THREADS) {
            int g  = n0 + i;
            float v  = (g < L_IN) ? xb[g] : 0.0f;
            int g2 = g + 1;
            float v2 = (g2 < L_IN) ? xb[g2] : 0.0f;
            xc[i] = __float2half_rn(v);
            xo[i] = __float2half_rn(v2);
        }
    }
    __syncthreads();

    // ---- per-lane address bases ----
    const int sub = lid >> 3;
    const uint32_t a_base = sbase + WS_OFF
        + (uint32_t)(((lid & 7) + (sub & 1) * 8) * A_STRIDE_B + (sub >> 1) * 16);
    const int sel = gid & 1;
    const uint32_t b_base = sbase + (sel ? XO_OFF : XC_OFF)
        + (uint32_t)(2 * (2 * tg + nw + gid - sel));

    float acc[NI][NJ][4];
    #pragma unroll
    for (int i = 0; i < NI; i++)
        #pragma unroll
        for (int j = 0; j < NJ; j++)
            #pragma unroll
            for (int c = 0; c < 4; c++) acc[i][j][c] = 0.0f;

    // ---- software-pipelined mainloop (asm volatile order = SASS order) ----
    uint32_t bh[NJ + 1], bhn[NJ + 1];
    uint32_t ahc[4], ahn[4];

    #pragma unroll
    for (int j = 0; j < NJ + 1; j++) bh[j] = lds32(b_base + (uint32_t)(j * 16));
    ldsm4(ahc, a_base);                       // i=0, s=0

    #pragma unroll 1
    for (int s = 0; s < NSTEPS; s++) {
        const uint32_t kb  = (uint32_t)s * 32;
        const uint32_t kbn = kb + 32;         // next step (s=15: reads row pad, unused)

        #pragma unroll
        for (int i = 0; i < NI; i++) {
            if (i < NI - 1) {
                ldsm4(ahn, a_base + (uint32_t)((i + 1) * 16 * A_STRIDE_B) + kb);
            } else {
                ldsm4(ahn, a_base + kbn);     // i=0 of next step
            }
            #pragma unroll
            for (int j = 0; j < NJ; j++) {
                mma16816(acc[i][j], ahc, bh[j], bh[j + 1]);
            }
            if (i == 0) {
                #pragma unroll
                for (int j = 0; j < NJ + 1; j++)
                    bhn[j] = lds32(b_base + kbn + (uint32_t)(j * 16));
            }
            #pragma unroll
            for (int r = 0; r < 4; r++) ahc[r] = ahn[r];
        }
        #pragma unroll
        for (int j = 0; j < NJ + 1; j++) bh[j] = bhn[j];
    }

    // ---- epilogue ----
    if (n0 + NT <= P_OUT) {
        // fast path: warp-private smem transpose -> fully coalesced STG.64
        const uint32_t epi = sbase + EPI_OFF + (uint32_t)(wid * EPI_WARP_B);
        #pragma unroll
        for (int i = 0; i < NI; i++) {
            #pragma unroll
            for (int j = 0; j < NJ; j++) {
                uint32_t cw = (uint32_t)(8 * j + 2 * tg);
                sts_v2(epi + (uint32_t)((gid * 40 + cw) * 4),
                       acc[i][j][0], acc[i][j][1]);
                sts_v2(epi + (uint32_t)(((gid + 8) * 40 + cw) * 4),
                       acc[i][j][2], acc[i][j][3]);
            }
            __syncwarp();
            #pragma unroll
            for (int q = 0; q < 8; q++) {
                int row = 2 * q + (lid >> 4);        // 0..15
                int col = (lid & 15) * 2;            // 0..30
                float2 v = lds_v2(epi + (uint32_t)((row * 40 + col) * 4));
                int f = 16 * i + row;
                *reinterpret_cast<float2*>(
                    out + ((size_t)b * N_FILT + f) * P_OUT + n0 + nw + col) = v;
            }
            __syncwarp();
        }
    } else {
        // tail tiles: guarded scalar path
        #pragma unroll
        for (int i = 0; i < NI; i++) {
            const int f0 = 16 * i + gid;
            float* o0 = out + ((size_t)b * N_FILT + f0) * P_OUT;
            float* o1 = out + ((size_t)b * N_FILT + f0 + 8) * P_OUT;
            #pragma unroll
            for (int j = 0; j < NJ; j++) {
                int p = n0 + nw + 8 * j + 2 * tg;
                if (p < P_OUT) {
                    *reinterpret_cast<float2*>(o0 + p) =
                        make_float2(acc[i][j][0], acc[i][j][1]);
                    *reinterpret_cast<float2*>(o1 + p) =
                        make_float2(acc[i][j][2], acc[i][j][3]);
                }
            }
        }
    }
}

// ================================ launch ================================
extern "C" void kernel_launch(void* const* d_in, const int* in_sizes, int n_in,
                              void* d_out, int out_size) {
    const float* x    = (const float*)d_in[0];
    const float* nf1  = (const float*)d_in[1];
    const float* nf2  = (const float*)d_in[2];
    const float* nf3  = (const float*)d_in[3];
    const float* nf4  = (const float*)d_in[4];
    const float* amp1 = (const float*)d_in[5];
    const float* amp2 = (const float*)d_in[6];
    float* out = (float*)d_out;

    static bool attr_set = false;
    if (!attr_set) {
        cudaFuncSetAttribute(conv_mma_kernel,
                             cudaFuncAttributeMaxDynamicSharedMemorySize, SMEM_TOTAL);
        attr_set = true;
    }

    build_filters_kernel<<<N_FILT, BF_THREADS>>>(nf1, nf2, nf3, nf4, amp1, amp2);

    dim3 grid((P_OUT + NT - 1) / NT, N_BATCH);   // 250 x 8
    conv_mma_kernel<<<grid, THREADS, SMEM_TOTAL>>>(x, out);
}